// round 15
// baseline (speedup 1.0000x reference)
#include <cuda_runtime.h>
#include <cuda_fp16.h>

#define BATCH  8
#define SEQ    1024
#define EMB    768
#define NHEADS 12
#define HDIM   64
#define E3     2304
#define MROWS  8192
#define SCALE  0.125f

// Scratch (no cudaMalloc allowed)
__device__ __half g_hs16[(size_t)MROWS * EMB];     // hidden fp16
__device__ __half g_qkvwt[(size_t)E3 * EMB];       // qkv_w^T  [n][k] fp16
__device__ __half g_projwt[(size_t)EMB * EMB];     // proj_w^T [n][k] fp16
__device__ __half g_qkv16[(size_t)MROWS * E3];     // QKV output fp16 (Q pre-scaled)
__device__ __half g_ctx16[(size_t)MROWS * EMB];    // attention output fp16

// ---------------------------------------------------------------------------
// helpers
// ---------------------------------------------------------------------------
__device__ __forceinline__ void mma_f16(float* d, const unsigned* a, const unsigned* b) {
    asm volatile(
        "mma.sync.aligned.m16n8k16.row.col.f32.f16.f16.f32 "
        "{%0,%1,%2,%3}, {%4,%5,%6,%7}, {%8,%9}, {%0,%1,%2,%3};\n"
        : "+f"(d[0]), "+f"(d[1]), "+f"(d[2]), "+f"(d[3])
        : "r"(a[0]), "r"(a[1]), "r"(a[2]), "r"(a[3]), "r"(b[0]), "r"(b[1]));
}
__device__ __forceinline__ void ldm_x4(unsigned* r, unsigned addr) {
    asm volatile("ldmatrix.sync.aligned.m8n8.x4.shared.b16 {%0,%1,%2,%3}, [%4];"
                 : "=r"(r[0]), "=r"(r[1]), "=r"(r[2]), "=r"(r[3]) : "r"(addr));
}
__device__ __forceinline__ void ldm_x4_t(unsigned* r, unsigned addr) {
    asm volatile("ldmatrix.sync.aligned.m8n8.x4.trans.shared.b16 {%0,%1,%2,%3}, [%4];"
                 : "=r"(r[0]), "=r"(r[1]), "=r"(r[2]), "=r"(r[3]) : "r"(addr));
}
__device__ __forceinline__ void cpa16(unsigned dst, const void* src) {
    asm volatile("cp.async.cg.shared.global [%0], [%1], 16;" :: "r"(dst), "l"(src));
}
__device__ __forceinline__ void cpa_commit() { asm volatile("cp.async.commit_group;"); }
template <int N> __device__ __forceinline__ void cpa_wait() {
    asm volatile("cp.async.wait_group %0;" :: "n"(N));
}
__device__ __forceinline__ unsigned smem_u32(const void* p) {
    return (unsigned)__cvta_generic_to_shared(p);
}

// ---------------------------------------------------------------------------
// prepass: fp32 -> fp16 elementwise
// ---------------------------------------------------------------------------
__global__ void cvt16_kernel(const float* __restrict__ src, __half* __restrict__ dst, int n4) {
    int i = blockIdx.x * blockDim.x + threadIdx.x;
    if (i < n4) {
        float4 v = ((const float4*)src)[i];
        __half2* d2 = (__half2*)dst;
        d2[i * 2]     = __floats2half2_rn(v.x, v.y);
        d2[i * 2 + 1] = __floats2half2_rn(v.z, v.w);
    }
}

// prepass: W[k][n] fp32 -> Wt[n][k] fp16 (32x32 tiles)
__global__ void transpose_cvt_kernel(const float* __restrict__ W, __half* __restrict__ Wt,
                                     int K, int N) {
    __shared__ float t[32][33];
    int k0 = blockIdx.y * 32, n0 = blockIdx.x * 32;
    int tx = threadIdx.x, ty = threadIdx.y;   // 32 x 8
#pragma unroll
    for (int i = 0; i < 4; i++)
        t[ty + i * 8][tx] = W[(size_t)(k0 + ty + i * 8) * N + n0 + tx];
    __syncthreads();
#pragma unroll
    for (int i = 0; i < 4; i++)
        Wt[(size_t)(n0 + ty + i * 8) * K + k0 + tx] = __float2half_rn(t[tx][ty + i * 8]);
}

// ---------------------------------------------------------------------------
// fp16 GEMM: C[M,N] = A[M,K] @ Bt[N,K]^T + bias.
// CTA tile 64(M)x128(N), BK=64, 2-stage cp.async ring.
// 8 warps 2(m)x4(n), warp tile 32x32 (R14's proven occupancy shape: ~80 regs,
// __launch_bounds__(256,3) -> 3 CTAs/SM). BK=64 halves barrier count (12
// iters) and exposes 4 independent k16 chains per stage for deeper ILP.
// Schedule: wait(kt) -> sync -> issue load kt+1 (overlaps compute) -> compute.
// Smem 2 stages x (64+128) x 72 halves = 55296 B -> 3 CTAs fit.
// Requires M%64==0, N%128==0, K%64==0 (true for both uses).
// ---------------------------------------------------------------------------
template <bool QKV>
__global__ __launch_bounds__(256, 3) void gemm_f16_kernel(
    const __half* __restrict__ A, const __half* __restrict__ Bt,
    const float* __restrict__ bias, void* __restrict__ Cv, int N, int K)
{
    extern __shared__ __half dsm[];
    // layout: A stages [2][64*72], then B stages [2][128*72]
    const unsigned aB = smem_u32(dsm);
    const unsigned bB = aB + 2 * 64 * 72 * 2;
    const unsigned aStage = 64 * 72 * 2;
    const unsigned bStage = 128 * 72 * 2;

    const int tid  = threadIdx.x;
    const int lane = tid & 31;
    const int wid  = tid >> 5;
    const int wm   = wid >> 2;          // 0..1 (32 rows each)
    const int wn   = wid & 3;           // 0..3 (32 cols each)
    const int r0   = lane >> 2;
    const int c0   = lane & 3;
    const int rowBase = blockIdx.y * 64;
    const int colBase = blockIdx.x * 128;

    // loaders (BK=64 => 8 chunks of 16B per row):
    //   A tile 64 rows  x 8 chunks = 512 -> 2 chunks/thread
    //   B tile 128 rows x 8 chunks = 1024 -> 4 chunks/thread
    const int a_row = tid >> 2;          // 0..63, 4 threads/row
    const int a_ch  = (tid & 3) * 2;     // chunks a_ch, a_ch+1
    const int b_row = tid >> 1;          // 0..127, 2 threads/row
    const int b_ch  = (tid & 1) * 4;     // chunks b_ch..b_ch+3

    const __half* Ap = A  + (size_t)(rowBase + a_row) * K + a_ch * 8;
    const __half* Bp = Bt + (size_t)(colBase + b_row) * K + b_ch * 8;

    const unsigned aDst = (unsigned)(a_row * 72 + a_ch * 8) * 2;
    const unsigned bDst = (unsigned)(b_row * 72 + b_ch * 8) * 2;

    float acc[2][8][4];
#pragma unroll
    for (int i = 0; i < 2; i++)
#pragma unroll
        for (int j = 0; j < 8; j++)
#pragma unroll
            for (int e = 0; e < 4; e++) acc[i][j][e] = 0.f;

    const int nkt = K / 64;   // 12

    // preload tile 0 into stage 0
    cpa16(aB + aDst,      Ap);
    cpa16(aB + aDst + 16, Ap + 8);
#pragma unroll
    for (int ch = 0; ch < 4; ch++)
        cpa16(bB + bDst + ch * 16, Bp + ch * 8);
    cpa_commit();

    const unsigned fragRow = (unsigned)(lane & 15);
    const unsigned fragK   = (unsigned)((lane >> 4) << 3);

    for (int kt = 0; kt < nkt; kt++) {
        cpa_wait<0>();        // tile kt resident (each thread's own copies)
        __syncthreads();      // all copies visible; stage (kt+1)&1 consumers done

        if (kt + 1 < nkt) {
            const int s2 = (kt + 1) & 1;
            const __half* Ap1 = Ap + (kt + 1) * 64;
            const __half* Bp1 = Bp + (kt + 1) * 64;
            cpa16(aB + s2 * aStage + aDst,      Ap1);
            cpa16(aB + s2 * aStage + aDst + 16, Ap1 + 8);
#pragma unroll
            for (int ch = 0; ch < 4; ch++)
                cpa16(bB + s2 * bStage + bDst + ch * 16, Bp1 + ch * 8);
            cpa_commit();
        }

        const unsigned as = aB + (kt & 1) * aStage;
        const unsigned bs = bB + (kt & 1) * bStage;
#pragma unroll
        for (int ks = 0; ks < 64; ks += 16) {
            unsigned af[2][4], bf[2][4];
#pragma unroll
            for (int mt = 0; mt < 2; mt++)
                ldm_x4(af[mt], as + ((wm * 32 + mt * 16 + fragRow) * 72 + ks + fragK) * 2);
#pragma unroll
            for (int nb = 0; nb < 2; nb++)
                ldm_x4(bf[nb], bs + ((wn * 32 + nb * 16 + fragRow) * 72 + ks + fragK) * 2);
#pragma unroll
            for (int mt = 0; mt < 2; mt++)
#pragma unroll
                for (int nb = 0; nb < 2; nb++)
#pragma unroll
                    for (int nt2 = 0; nt2 < 2; nt2++) {
                        unsigned b2[2] = {bf[nb][nt2], bf[nb][2 + nt2]};
                        mma_f16(acc[mt][nb * 2 + nt2], af[mt], b2);
                    }
        }
    }

    // epilogue
#pragma unroll
    for (int nn = 0; nn < 4; nn++) {
        int col = colBase + wn * 32 + (nn >> 1) * 16 + (nn & 1) * 8 + (c0 << 1);
        float2 bv = *(const float2*)(bias + col);
        float sc = (QKV && col < EMB) ? SCALE : 1.0f;
#pragma unroll
        for (int mt = 0; mt < 2; mt++) {
            int row = rowBase + wm * 32 + mt * 16 + r0;
            float x0 = (acc[mt][nn][0] + bv.x) * sc;
            float x1 = (acc[mt][nn][1] + bv.y) * sc;
            float x2 = (acc[mt][nn][2] + bv.x) * sc;
            float x3 = (acc[mt][nn][3] + bv.y) * sc;
            if (QKV) {
                __half2* C = (__half2*)Cv;
                C[((size_t)row * N + col) >> 1]       = __floats2half2_rn(x0, x1);
                C[((size_t)(row + 8) * N + col) >> 1] = __floats2half2_rn(x2, x3);
            } else {
                float* C = (float*)Cv;
                *(float2*)(C + (size_t)row * N + col)       = make_float2(x0, x1);
                *(float2*)(C + (size_t)(row + 8) * N + col) = make_float2(x2, x3);
            }
        }
    }
}

// ---------------------------------------------------------------------------
// fp16 tensor-core flash attention, 3-stage K/V cp.async ring.
// (unchanged from R14 passing version)
// ---------------------------------------------------------------------------
__global__ __launch_bounds__(256) void attn_f16_kernel(const __half* __restrict__ qkv,
                                                       __half* __restrict__ ctx)
{
    extern __shared__ __half asm_[];
    const unsigned qsB = smem_u32(asm_);               // [128][72]
    const unsigned kB  = qsB + 128 * 72 * 2;           // 3 x [64][72]
    const unsigned vB  = kB + 3 * 64 * 72 * 2;         // 3 x [64][72]
    const unsigned kvStage = 64 * 72 * 2;

    const int tid  = threadIdx.x;
    const int lane = tid & 31;
    const int w    = tid >> 5;
    const int r0   = lane >> 2;
    const int c0   = lane & 3;
    const int qrow = w * 16 + r0;

    const int qt = blockIdx.x;
    const int h  = blockIdx.y;
    const int b  = blockIdx.z;

    const unsigned fragRow = (unsigned)(lane & 15);
    const unsigned fragK   = (unsigned)((lane >> 4) << 3);

    const __half* qg = qkv + (size_t)(b * SEQ + qt * 128) * E3 + h * HDIM;
    {
        int row = tid >> 1;
        int off = (tid & 1) * 4;
#pragma unroll
        for (int i = 0; i < 4; i++)
            cpa16(qsB + (unsigned)(row * 72 + (off + i) * 8) * 2,
                  qg + (size_t)row * E3 + (off + i) * 8);
        cpa_commit();
        cpa_wait<0>();
        __syncthreads();
    }

    unsigned qf[4][4];
#pragma unroll
    for (int ks = 0; ks < 4; ks++)
        ldm_x4(qf[ks], qsB + ((w * 16 + fragRow) * 72 + ks * 16 + fragK) * 2);

    float accO[8][4];
#pragma unroll
    for (int nt = 0; nt < 8; nt++)
#pragma unroll
        for (int e = 0; e < 4; e++) accO[nt][e] = 0.f;
    float m0 = -1e30f, m1 = -1e30f, l0 = 0.f, l1 = 0.f;

    const __half* kg = qkv + (size_t)b * SEQ * E3 + EMB     + h * HDIM;
    const __half* vg = qkv + (size_t)b * SEQ * E3 + 2 * EMB + h * HDIM;

    const int ld_row = tid >> 2;
    const int ld_off = (tid & 3) * 2;
    const size_t ldbase = (size_t)ld_row * E3 + ld_off * 8;
    const unsigned dOff = (unsigned)(ld_row * 72 + ld_off * 8) * 2;

#pragma unroll
    for (int t = 0; t < 2; t++) {
        const __half* kb = kg + (size_t)(t * 64) * E3 + ldbase;
        const __half* vb = vg + (size_t)(t * 64) * E3 + ldbase;
        cpa16(kB + t * kvStage + dOff,      kb);
        cpa16(kB + t * kvStage + dOff + 16, kb + 8);
        cpa16(vB + t * kvStage + dOff,      vb);
        cpa16(vB + t * kvStage + dOff + 16, vb + 8);
        cpa_commit();
    }

    for (int kt = 0; kt < 16; kt++) {
        if (kt + 1 < 16) cpa_wait<1>(); else cpa_wait<0>();
        __syncthreads();

        if (kt + 2 < 16) {
            const int s2 = (kt + 2) % 3;
            const __half* kb = kg + (size_t)((kt + 2) * 64) * E3 + ldbase;
            const __half* vb = vg + (size_t)((kt + 2) * 64) * E3 + ldbase;
            cpa16(kB + s2 * kvStage + dOff,      kb);
            cpa16(kB + s2 * kvStage + dOff + 16, kb + 8);
            cpa16(vB + s2 * kvStage + dOff,      vb);
            cpa16(vB + s2 * kvStage + dOff + 16, vb + 8);
            cpa_commit();
        }

        const unsigned ksS = kB + (kt % 3) * kvStage;
        const unsigned vsS = vB + (kt % 3) * kvStage;

        float accS[8][4];
#pragma unroll
        for (int nt = 0; nt < 8; nt++)
#pragma unroll
            for (int e = 0; e < 4; e++) accS[nt][e] = 0.f;

#pragma unroll
        for (int ks = 0; ks < 4; ks++) {
#pragma unroll
            for (int np = 0; np < 4; np++) {
                unsigned bf[4];
                ldm_x4(bf, ksS + ((np * 16 + fragRow) * 72 + ks * 16 + fragK) * 2);
                unsigned b0[2] = {bf[0], bf[2]};
                unsigned b1[2] = {bf[1], bf[3]};
                mma_f16(accS[np * 2],     qf[ks], b0);
                mma_f16(accS[np * 2 + 1], qf[ks], b1);
            }
        }

        float mx0 = -1e30f, mx1 = -1e30f;
#pragma unroll
        for (int nt = 0; nt < 8; nt++) {
            mx0 = fmaxf(mx0, fmaxf(accS[nt][0], accS[nt][1]));
            mx1 = fmaxf(mx1, fmaxf(accS[nt][2], accS[nt][3]));
        }
#pragma unroll
        for (int off = 1; off < 4; off <<= 1) {
            mx0 = fmaxf(mx0, __shfl_xor_sync(0xffffffffu, mx0, off));
            mx1 = fmaxf(mx1, __shfl_xor_sync(0xffffffffu, mx1, off));
        }
        float mn0 = fmaxf(m0, mx0), mn1 = fmaxf(m1, mx1);
        float alpha0 = __expf(m0 - mn0), alpha1 = __expf(m1 - mn1);
        m0 = mn0; m1 = mn1;

        __syncwarp();

        float s0 = 0.f, s1 = 0.f;
        __half2* P2 = (__half2*)asm_;
#pragma unroll
        for (int nt = 0; nt < 8; nt++) {
            float p0 = __expf(accS[nt][0] - mn0);
            float p1 = __expf(accS[nt][1] - mn0);
            float p2 = __expf(accS[nt][2] - mn1);
            float p3 = __expf(accS[nt][3] - mn1);
            s0 += p0 + p1;
            s1 += p2 + p3;
            int cl = nt * 8 + (c0 << 1);
            P2[(qrow * 72 + cl) >> 1]       = __floats2half2_rn(p0, p1);
            P2[((qrow + 8) * 72 + cl) >> 1] = __floats2half2_rn(p2, p3);
        }
#pragma unroll
        for (int off = 1; off < 4; off <<= 1) {
            s0 += __shfl_xor_sync(0xffffffffu, s0, off);
            s1 += __shfl_xor_sync(0xffffffffu, s1, off);
        }
        l0 = l0 * alpha0 + s0;
        l1 = l1 * alpha1 + s1;
#pragma unroll
        for (int nt = 0; nt < 8; nt++) {
            accO[nt][0] *= alpha0; accO[nt][1] *= alpha0;
            accO[nt][2] *= alpha1; accO[nt][3] *= alpha1;
        }
        __syncwarp();

#pragma unroll
        for (int ks = 0; ks < 4; ks++) {
            unsigned pf[4];
            ldm_x4(pf, qsB + ((w * 16 + fragRow) * 72 + ks * 16 + fragK) * 2);
#pragma unroll
            for (int np = 0; np < 4; np++) {
                unsigned bf[4];
                ldm_x4_t(bf, vsS + ((ks * 16 + fragRow) * 72 + np * 16 + fragK) * 2);
                unsigned b0[2] = {bf[0], bf[1]};
                unsigned b1[2] = {bf[2], bf[3]};
                mma_f16(accO[np * 2],     pf, b0);
                mma_f16(accO[np * 2 + 1], pf, b1);
            }
        }
    }

    float inv0 = 1.f / l0, inv1 = 1.f / l1;
    __half2* ob = (__half2*)(ctx + (size_t)(b * SEQ + qt * 128) * EMB + h * HDIM);
#pragma unroll
    for (int nt = 0; nt < 8; nt++) {
        int col = nt * 8 + (c0 << 1);
        ob[((size_t)qrow * EMB + col) >> 1] =
            __floats2half2_rn(accO[nt][0] * inv0, accO[nt][1] * inv0);
        ob[((size_t)(qrow + 8) * EMB + col) >> 1] =
            __floats2half2_rn(accO[nt][2] * inv1, accO[nt][3] * inv1);
    }
}

// ---------------------------------------------------------------------------
extern "C" void kernel_launch(void* const* d_in, const int* in_sizes, int n_in,
                              void* d_out, int out_size)
{
    const float* hs     = (const float*)d_in[0];
    const float* qkv_w  = (const float*)d_in[1];
    const float* qkv_b  = (const float*)d_in[2];
    const float* proj_w = (const float*)d_in[3];
    const float* proj_b = (const float*)d_in[4];
    float* out = (float*)d_out;

    __half *hs16, *qkvwt, *projwt, *qkv16, *ctx16;
    cudaGetSymbolAddress((void**)&hs16,   g_hs16);
    cudaGetSymbolAddress((void**)&qkvwt,  g_qkvwt);
    cudaGetSymbolAddress((void**)&projwt, g_projwt);
    cudaGetSymbolAddress((void**)&qkv16,  g_qkv16);
    cudaGetSymbolAddress((void**)&ctx16,  g_ctx16);

    const int gemm_smem = 2 * (64 + 128) * 72 * 2;                // 55296 B
    const int attn_smem = (128 * 72 + 6 * 64 * 72) * 2;           // 73728 B
    cudaFuncSetAttribute(gemm_f16_kernel<true>,
                         cudaFuncAttributeMaxDynamicSharedMemorySize, gemm_smem);
    cudaFuncSetAttribute(gemm_f16_kernel<false>,
                         cudaFuncAttributeMaxDynamicSharedMemorySize, gemm_smem);
    cudaFuncSetAttribute(attn_f16_kernel,
                         cudaFuncAttributeMaxDynamicSharedMemorySize, attn_smem);

    // prepass: convert / transpose to fp16
    {
        int n4 = MROWS * EMB / 4;
        cvt16_kernel<<<(n4 + 255) / 256, 256>>>(hs, hs16, n4);
        transpose_cvt_kernel<<<dim3(E3 / 32, EMB / 32), dim3(32, 8)>>>(qkv_w, qkvwt, EMB, E3);
        transpose_cvt_kernel<<<dim3(EMB / 32, EMB / 32), dim3(32, 8)>>>(proj_w, projwt, EMB, EMB);
    }

    // 1) QKV projection (fp16 out, Q pre-scaled)
    gemm_f16_kernel<true><<<dim3(E3 / 128, MROWS / 64), 256, gemm_smem>>>(
        hs16, qkvwt, qkv_b, qkv16, E3, EMB);

    // 2) fp16 tensor-core flash attention
    attn_f16_kernel<<<dim3(SEQ / 128, NHEADS, BATCH), 256, attn_smem>>>(qkv16, ctx16);

    // 3) output projection (fp32 out)
    gemm_f16_kernel<false><<<dim3(EMB / 128, MROWS / 64), 256, gemm_smem>>>(
        ctx16, projwt, proj_b, out, EMB, EMB);
}

// round 16
// speedup vs baseline: 1.1163x; 1.1163x over previous
#include <cuda_runtime.h>
#include <cuda_fp16.h>

#define BATCH  8
#define SEQ    1024
#define EMB    768
#define NHEADS 12
#define HDIM   64
#define E3     2304
#define MROWS  8192
#define SCALE  0.125f

// Scratch (no cudaMalloc allowed)
__device__ __half g_hs16[(size_t)MROWS * EMB];     // hidden fp16
__device__ __half g_qkvwt[(size_t)E3 * EMB];       // qkv_w^T  [n][k] fp16
__device__ __half g_projwt[(size_t)EMB * EMB];     // proj_w^T [n][k] fp16
__device__ __half g_qkv16[(size_t)MROWS * E3];     // QKV output fp16 (Q pre-scaled)
__device__ __half g_ctx16[(size_t)MROWS * EMB];    // attention output fp16

// ---------------------------------------------------------------------------
// helpers
// ---------------------------------------------------------------------------
__device__ __forceinline__ void mma_f16(float* d, const unsigned* a, const unsigned* b) {
    asm volatile(
        "mma.sync.aligned.m16n8k16.row.col.f32.f16.f16.f32 "
        "{%0,%1,%2,%3}, {%4,%5,%6,%7}, {%8,%9}, {%0,%1,%2,%3};\n"
        : "+f"(d[0]), "+f"(d[1]), "+f"(d[2]), "+f"(d[3])
        : "r"(a[0]), "r"(a[1]), "r"(a[2]), "r"(a[3]), "r"(b[0]), "r"(b[1]));
}
__device__ __forceinline__ void ldm_x4(unsigned* r, unsigned addr) {
    asm volatile("ldmatrix.sync.aligned.m8n8.x4.shared.b16 {%0,%1,%2,%3}, [%4];"
                 : "=r"(r[0]), "=r"(r[1]), "=r"(r[2]), "=r"(r[3]) : "r"(addr));
}
__device__ __forceinline__ void ldm_x4_t(unsigned* r, unsigned addr) {
    asm volatile("ldmatrix.sync.aligned.m8n8.x4.trans.shared.b16 {%0,%1,%2,%3}, [%4];"
                 : "=r"(r[0]), "=r"(r[1]), "=r"(r[2]), "=r"(r[3]) : "r"(addr));
}
__device__ __forceinline__ void cpa16(unsigned dst, const void* src) {
    asm volatile("cp.async.cg.shared.global [%0], [%1], 16;" :: "r"(dst), "l"(src));
}
__device__ __forceinline__ void cpa_commit() { asm volatile("cp.async.commit_group;"); }
template <int N> __device__ __forceinline__ void cpa_wait() {
    asm volatile("cp.async.wait_group %0;" :: "n"(N));
}
__device__ __forceinline__ unsigned smem_u32(const void* p) {
    return (unsigned)__cvta_generic_to_shared(p);
}
__device__ __forceinline__ unsigned packh2(float a, float b) {
    __half2 h = __floats2half2_rn(a, b);
    return *(unsigned*)&h;
}

// ---------------------------------------------------------------------------
// prepass: fp32 -> fp16 elementwise
// ---------------------------------------------------------------------------
__global__ void cvt16_kernel(const float* __restrict__ src, __half* __restrict__ dst, int n4) {
    int i = blockIdx.x * blockDim.x + threadIdx.x;
    if (i < n4) {
        float4 v = ((const float4*)src)[i];
        __half2* d2 = (__half2*)dst;
        d2[i * 2]     = __floats2half2_rn(v.x, v.y);
        d2[i * 2 + 1] = __floats2half2_rn(v.z, v.w);
    }
}

// prepass: W[k][n] fp32 -> Wt[n][k] fp16 (32x32 tiles)
__global__ void transpose_cvt_kernel(const float* __restrict__ W, __half* __restrict__ Wt,
                                     int K, int N) {
    __shared__ float t[32][33];
    int k0 = blockIdx.y * 32, n0 = blockIdx.x * 32;
    int tx = threadIdx.x, ty = threadIdx.y;   // 32 x 8
#pragma unroll
    for (int i = 0; i < 4; i++)
        t[ty + i * 8][tx] = W[(size_t)(k0 + ty + i * 8) * N + n0 + tx];
    __syncthreads();
#pragma unroll
    for (int i = 0; i < 4; i++)
        Wt[(size_t)(n0 + ty + i * 8) * K + k0 + tx] = __float2half_rn(t[tx][ty + i * 8]);
}

// ---------------------------------------------------------------------------
// fp16 GEMM (exact R14 config: CTA 64x128, BK=32, 3-stage ring, wait<1>,
// warp tile 32x32, __launch_bounds__(256,3) -> 3 CTAs/SM, stride-40 smem).
// ---------------------------------------------------------------------------
template <bool QKV>
__global__ __launch_bounds__(256, 3) void gemm_f16_kernel(
    const __half* __restrict__ A, const __half* __restrict__ Bt,
    const float* __restrict__ bias, void* __restrict__ Cv, int N, int K)
{
    extern __shared__ __half dsm[];
    const unsigned aB = smem_u32(dsm);
    const unsigned bB = aB + 3 * 64 * 40 * 2;
    const unsigned aStage = 64 * 40 * 2;
    const unsigned bStage = 128 * 40 * 2;

    const int tid  = threadIdx.x;
    const int lane = tid & 31;
    const int wid  = tid >> 5;
    const int wm   = wid >> 2;
    const int wn   = wid & 3;
    const int r0   = lane >> 2;
    const int c0   = lane & 3;
    const int rowBase = blockIdx.y * 64;
    const int colBase = blockIdx.x * 128;

    const int a_row = tid >> 2;
    const int a_ch  = tid & 3;
    const int b_row = tid >> 1;
    const int b_ch  = (tid & 1) * 2;

    const __half* Ap = A  + (size_t)(rowBase + a_row) * K + a_ch * 8;
    const __half* Bp = Bt + (size_t)(colBase + b_row) * K + b_ch * 8;

    const unsigned aDst = (unsigned)(a_row * 40 + a_ch * 8) * 2;
    const unsigned bDst = (unsigned)(b_row * 40 + b_ch * 8) * 2;

    float acc[2][8][4];
#pragma unroll
    for (int i = 0; i < 2; i++)
#pragma unroll
        for (int j = 0; j < 8; j++)
#pragma unroll
            for (int e = 0; e < 4; e++) acc[i][j][e] = 0.f;

    const int nkt = K / 32;

#pragma unroll
    for (int t = 0; t < 2; t++) {
        cpa16(aB + t * aStage + aDst, Ap + t * 32);
        cpa16(bB + t * bStage + bDst,      Bp + t * 32);
        cpa16(bB + t * bStage + bDst + 16, Bp + t * 32 + 8);
        cpa_commit();
    }

    const unsigned fragRow = (unsigned)(lane & 15);
    const unsigned fragK   = (unsigned)((lane >> 4) << 3);

    for (int kt = 0; kt < nkt; kt++) {
        if (kt + 1 < nkt) cpa_wait<1>(); else cpa_wait<0>();
        __syncthreads();

        if (kt + 2 < nkt) {
            const int s2 = (kt + 2) % 3;
            cpa16(aB + s2 * aStage + aDst, Ap + (kt + 2) * 32);
            cpa16(bB + s2 * bStage + bDst,      Bp + (kt + 2) * 32);
            cpa16(bB + s2 * bStage + bDst + 16, Bp + (kt + 2) * 32 + 8);
            cpa_commit();
        }

        const unsigned as = aB + (kt % 3) * aStage;
        const unsigned bs = bB + (kt % 3) * bStage;
#pragma unroll
        for (int ks = 0; ks < 32; ks += 16) {
            unsigned af[2][4], bf[2][4];
#pragma unroll
            for (int mt = 0; mt < 2; mt++)
                ldm_x4(af[mt], as + ((wm * 32 + mt * 16 + fragRow) * 40 + ks + fragK) * 2);
#pragma unroll
            for (int nb = 0; nb < 2; nb++)
                ldm_x4(bf[nb], bs + ((wn * 32 + nb * 16 + fragRow) * 40 + ks + fragK) * 2);
#pragma unroll
            for (int mt = 0; mt < 2; mt++)
#pragma unroll
                for (int nb = 0; nb < 2; nb++)
#pragma unroll
                    for (int nt2 = 0; nt2 < 2; nt2++) {
                        unsigned b2[2] = {bf[nb][nt2], bf[nb][2 + nt2]};
                        mma_f16(acc[mt][nb * 2 + nt2], af[mt], b2);
                    }
        }
    }

#pragma unroll
    for (int nn = 0; nn < 4; nn++) {
        int col = colBase + wn * 32 + (nn >> 1) * 16 + (nn & 1) * 8 + (c0 << 1);
        float2 bv = *(const float2*)(bias + col);
        float sc = (QKV && col < EMB) ? SCALE : 1.0f;
#pragma unroll
        for (int mt = 0; mt < 2; mt++) {
            int row = rowBase + wm * 32 + mt * 16 + r0;
            float x0 = (acc[mt][nn][0] + bv.x) * sc;
            float x1 = (acc[mt][nn][1] + bv.y) * sc;
            float x2 = (acc[mt][nn][2] + bv.x) * sc;
            float x3 = (acc[mt][nn][3] + bv.y) * sc;
            if (QKV) {
                __half2* C = (__half2*)Cv;
                C[((size_t)row * N + col) >> 1]       = __floats2half2_rn(x0, x1);
                C[((size_t)(row + 8) * N + col) >> 1] = __floats2half2_rn(x2, x3);
            } else {
                float* C = (float*)Cv;
                *(float2*)(C + (size_t)row * N + col)       = make_float2(x0, x1);
                *(float2*)(C + (size_t)(row + 8) * N + col) = make_float2(x2, x3);
            }
        }
    }
}

// ---------------------------------------------------------------------------
// fp16 flash attention, 3-stage K/V ring, REGISTER-RESIDENT P.
// The S-phase D-fragment layout (d0,d1=row r0 cols 2c0..+1; d2,d3=row r0+8)
// equals the PV A-fragment layout, so softmaxed P packs straight into
// half2 A-fragments: no P smem stores, no P ldmatrix, no __syncwarp.
// ---------------------------------------------------------------------------
__global__ __launch_bounds__(256) void attn_f16_kernel(const __half* __restrict__ qkv,
                                                       __half* __restrict__ ctx)
{
    extern __shared__ __half asm_[];
    const unsigned qsB = smem_u32(asm_);               // [128][72]
    const unsigned kB  = qsB + 128 * 72 * 2;           // 3 x [64][72]
    const unsigned vB  = kB + 3 * 64 * 72 * 2;         // 3 x [64][72]
    const unsigned kvStage = 64 * 72 * 2;

    const int tid  = threadIdx.x;
    const int lane = tid & 31;
    const int w    = tid >> 5;

    const int qt = blockIdx.x;
    const int h  = blockIdx.y;
    const int b  = blockIdx.z;

    const unsigned fragRow = (unsigned)(lane & 15);
    const unsigned fragK   = (unsigned)((lane >> 4) << 3);
    const int r0 = lane >> 2;
    const int c0 = lane & 3;
    const int qrow = w * 16 + r0;

    // ---- load Q tile ----
    const __half* qg = qkv + (size_t)(b * SEQ + qt * 128) * E3 + h * HDIM;
    {
        int row = tid >> 1;
        int off = (tid & 1) * 4;
#pragma unroll
        for (int i = 0; i < 4; i++)
            cpa16(qsB + (unsigned)(row * 72 + (off + i) * 8) * 2,
                  qg + (size_t)row * E3 + (off + i) * 8);
        cpa_commit();
        cpa_wait<0>();
        __syncthreads();
    }

    unsigned qf[4][4];
#pragma unroll
    for (int ks = 0; ks < 4; ks++)
        ldm_x4(qf[ks], qsB + ((w * 16 + fragRow) * 72 + ks * 16 + fragK) * 2);

    float accO[8][4];
#pragma unroll
    for (int nt = 0; nt < 8; nt++)
#pragma unroll
        for (int e = 0; e < 4; e++) accO[nt][e] = 0.f;
    float m0 = -1e30f, m1 = -1e30f, l0 = 0.f, l1 = 0.f;

    const __half* kg = qkv + (size_t)b * SEQ * E3 + EMB     + h * HDIM;
    const __half* vg = qkv + (size_t)b * SEQ * E3 + 2 * EMB + h * HDIM;

    const int ld_row = tid >> 2;
    const int ld_off = (tid & 3) * 2;
    const size_t ldbase = (size_t)ld_row * E3 + ld_off * 8;
    const unsigned dOff = (unsigned)(ld_row * 72 + ld_off * 8) * 2;

#pragma unroll
    for (int t = 0; t < 2; t++) {
        const __half* kb = kg + (size_t)(t * 64) * E3 + ldbase;
        const __half* vb = vg + (size_t)(t * 64) * E3 + ldbase;
        cpa16(kB + t * kvStage + dOff,      kb);
        cpa16(kB + t * kvStage + dOff + 16, kb + 8);
        cpa16(vB + t * kvStage + dOff,      vb);
        cpa16(vB + t * kvStage + dOff + 16, vb + 8);
        cpa_commit();
    }

    for (int kt = 0; kt < 16; kt++) {
        if (kt + 1 < 16) cpa_wait<1>(); else cpa_wait<0>();
        __syncthreads();

        if (kt + 2 < 16) {
            const int s2 = (kt + 2) % 3;
            const __half* kb = kg + (size_t)((kt + 2) * 64) * E3 + ldbase;
            const __half* vb = vg + (size_t)((kt + 2) * 64) * E3 + ldbase;
            cpa16(kB + s2 * kvStage + dOff,      kb);
            cpa16(kB + s2 * kvStage + dOff + 16, kb + 8);
            cpa16(vB + s2 * kvStage + dOff,      vb);
            cpa16(vB + s2 * kvStage + dOff + 16, vb + 8);
            cpa_commit();
        }

        const unsigned ksS = kB + (kt % 3) * kvStage;
        const unsigned vsS = vB + (kt % 3) * kvStage;

        // ---- S = Q K^T : 16 rows x 64 keys per warp ----
        float accS[8][4];
#pragma unroll
        for (int nt = 0; nt < 8; nt++)
#pragma unroll
            for (int e = 0; e < 4; e++) accS[nt][e] = 0.f;

#pragma unroll
        for (int ks = 0; ks < 4; ks++) {
#pragma unroll
            for (int np = 0; np < 4; np++) {
                unsigned bf[4];
                ldm_x4(bf, ksS + ((np * 16 + fragRow) * 72 + ks * 16 + fragK) * 2);
                unsigned b0[2] = {bf[0], bf[2]};
                unsigned b1[2] = {bf[1], bf[3]};
                mma_f16(accS[np * 2],     qf[ks], b0);
                mma_f16(accS[np * 2 + 1], qf[ks], b1);
            }
        }

        // ---- online softmax (rows qrow, qrow+8) ----
        float mx0 = -1e30f, mx1 = -1e30f;
#pragma unroll
        for (int nt = 0; nt < 8; nt++) {
            mx0 = fmaxf(mx0, fmaxf(accS[nt][0], accS[nt][1]));
            mx1 = fmaxf(mx1, fmaxf(accS[nt][2], accS[nt][3]));
        }
#pragma unroll
        for (int off = 1; off < 4; off <<= 1) {
            mx0 = fmaxf(mx0, __shfl_xor_sync(0xffffffffu, mx0, off));
            mx1 = fmaxf(mx1, __shfl_xor_sync(0xffffffffu, mx1, off));
        }
        float mn0 = fmaxf(m0, mx0), mn1 = fmaxf(m1, mx1);
        float alpha0 = __expf(m0 - mn0), alpha1 = __expf(m1 - mn1);
        m0 = mn0; m1 = mn1;

        // ---- P in registers: D-frag layout == A-frag layout ----
        unsigned pP[8][2];   // pP[nt][0] = h2(row r0), pP[nt][1] = h2(row r0+8)
        float s0 = 0.f, s1 = 0.f;
#pragma unroll
        for (int nt = 0; nt < 8; nt++) {
            float p0 = __expf(accS[nt][0] - mn0);
            float p1 = __expf(accS[nt][1] - mn0);
            float p2 = __expf(accS[nt][2] - mn1);
            float p3 = __expf(accS[nt][3] - mn1);
            s0 += p0 + p1;
            s1 += p2 + p3;
            pP[nt][0] = packh2(p0, p1);
            pP[nt][1] = packh2(p2, p3);
        }
#pragma unroll
        for (int off = 1; off < 4; off <<= 1) {
            s0 += __shfl_xor_sync(0xffffffffu, s0, off);
            s1 += __shfl_xor_sync(0xffffffffu, s1, off);
        }
        l0 = l0 * alpha0 + s0;
        l1 = l1 * alpha1 + s1;
#pragma unroll
        for (int nt = 0; nt < 8; nt++) {
            accO[nt][0] *= alpha0; accO[nt][1] *= alpha0;
            accO[nt][2] *= alpha1; accO[nt][3] *= alpha1;
        }

        // ---- O += P V : A-frags straight from registers ----
#pragma unroll
        for (int ks = 0; ks < 4; ks++) {
            unsigned pf[4] = {pP[2 * ks][0], pP[2 * ks][1],
                              pP[2 * ks + 1][0], pP[2 * ks + 1][1]};
#pragma unroll
            for (int np = 0; np < 4; np++) {
                unsigned bf[4];
                ldm_x4_t(bf, vsS + ((ks * 16 + fragRow) * 72 + np * 16 + fragK) * 2);
                unsigned b0[2] = {bf[0], bf[1]};
                unsigned b1[2] = {bf[2], bf[3]};
                mma_f16(accO[np * 2],     pf, b0);
                mma_f16(accO[np * 2 + 1], pf, b1);
            }
        }
    }

    // ---- normalize + write ctx16 ----
    float inv0 = 1.f / l0, inv1 = 1.f / l1;
    __half2* ob = (__half2*)(ctx + (size_t)(b * SEQ + qt * 128) * EMB + h * HDIM);
#pragma unroll
    for (int nt = 0; nt < 8; nt++) {
        int col = nt * 8 + (c0 << 1);
        ob[((size_t)qrow * EMB + col) >> 1] =
            __floats2half2_rn(accO[nt][0] * inv0, accO[nt][1] * inv0);
        ob[((size_t)(qrow + 8) * EMB + col) >> 1] =
            __floats2half2_rn(accO[nt][2] * inv1, accO[nt][3] * inv1);
    }
}

// ---------------------------------------------------------------------------
extern "C" void kernel_launch(void* const* d_in, const int* in_sizes, int n_in,
                              void* d_out, int out_size)
{
    const float* hs     = (const float*)d_in[0];
    const float* qkv_w  = (const float*)d_in[1];
    const float* qkv_b  = (const float*)d_in[2];
    const float* proj_w = (const float*)d_in[3];
    const float* proj_b = (const float*)d_in[4];
    float* out = (float*)d_out;

    __half *hs16, *qkvwt, *projwt, *qkv16, *ctx16;
    cudaGetSymbolAddress((void**)&hs16,   g_hs16);
    cudaGetSymbolAddress((void**)&qkvwt,  g_qkvwt);
    cudaGetSymbolAddress((void**)&projwt, g_projwt);
    cudaGetSymbolAddress((void**)&qkv16,  g_qkv16);
    cudaGetSymbolAddress((void**)&ctx16,  g_ctx16);

    const int gemm_smem = 3 * (64 + 128) * 40 * 2;                // 46080 B
    const int attn_smem = (128 * 72 + 6 * 64 * 72) * 2;           // 73728 B
    cudaFuncSetAttribute(gemm_f16_kernel<true>,
                         cudaFuncAttributeMaxDynamicSharedMemorySize, gemm_smem);
    cudaFuncSetAttribute(gemm_f16_kernel<false>,
                         cudaFuncAttributeMaxDynamicSharedMemorySize, gemm_smem);
    cudaFuncSetAttribute(attn_f16_kernel,
                         cudaFuncAttributeMaxDynamicSharedMemorySize, attn_smem);

    // prepass: convert / transpose to fp16
    {
        int n4 = MROWS * EMB / 4;
        cvt16_kernel<<<(n4 + 255) / 256, 256>>>(hs, hs16, n4);
        transpose_cvt_kernel<<<dim3(E3 / 32, EMB / 32), dim3(32, 8)>>>(qkv_w, qkvwt, EMB, E3);
        transpose_cvt_kernel<<<dim3(EMB / 32, EMB / 32), dim3(32, 8)>>>(proj_w, projwt, EMB, EMB);
    }

    // 1) QKV projection (fp16 out, Q pre-scaled)
    gemm_f16_kernel<true><<<dim3(E3 / 128, MROWS / 64), 256, gemm_smem>>>(
        hs16, qkvwt, qkv_b, qkv16, E3, EMB);

    // 2) fp16 tensor-core flash attention (register-resident P)
    attn_f16_kernel<<<dim3(SEQ / 128, NHEADS, BATCH), 256, attn_smem>>>(qkv16, ctx16);

    // 3) output projection (fp32 out)
    gemm_f16_kernel<false><<<dim3(EMB / 128, MROWS / 64), 256, gemm_smem>>>(
        ctx16, projwt, proj_b, out, EMB, EMB);
}

// round 17
// speedup vs baseline: 1.1610x; 1.0400x over previous
#include <cuda_runtime.h>
#include <cuda_fp16.h>

#define BATCH  8
#define SEQ    1024
#define EMB    768
#define NHEADS 12
#define HDIM   64
#define E3     2304
#define MROWS  8192
// Q prescale: attention SCALE folded with log2(e) for base-2 softmax
#define QSCALE 0.1803368801111204f   // 0.125 * 1.4426950408889634

// Scratch (no cudaMalloc allowed)
__device__ __half g_hs16[(size_t)MROWS * EMB];     // hidden fp16
__device__ __half g_qkvwt[(size_t)E3 * EMB];       // qkv_w^T  [n][k] fp16
__device__ __half g_projwt[(size_t)EMB * EMB];     // proj_w^T [n][k] fp16
__device__ __half g_qkv16[(size_t)MROWS * E3];     // QKV output fp16 (Q pre-scaled)
__device__ __half g_ctx16[(size_t)MROWS * EMB];    // attention output fp16

// ---------------------------------------------------------------------------
// helpers
// ---------------------------------------------------------------------------
__device__ __forceinline__ void mma_f16(float* d, const unsigned* a, const unsigned* b) {
    asm volatile(
        "mma.sync.aligned.m16n8k16.row.col.f32.f16.f16.f32 "
        "{%0,%1,%2,%3}, {%4,%5,%6,%7}, {%8,%9}, {%0,%1,%2,%3};\n"
        : "+f"(d[0]), "+f"(d[1]), "+f"(d[2]), "+f"(d[3])
        : "r"(a[0]), "r"(a[1]), "r"(a[2]), "r"(a[3]), "r"(b[0]), "r"(b[1]));
}
__device__ __forceinline__ void ldm_x4(unsigned* r, unsigned addr) {
    asm volatile("ldmatrix.sync.aligned.m8n8.x4.shared.b16 {%0,%1,%2,%3}, [%4];"
                 : "=r"(r[0]), "=r"(r[1]), "=r"(r[2]), "=r"(r[3]) : "r"(addr));
}
__device__ __forceinline__ void ldm_x4_t(unsigned* r, unsigned addr) {
    asm volatile("ldmatrix.sync.aligned.m8n8.x4.trans.shared.b16 {%0,%1,%2,%3}, [%4];"
                 : "=r"(r[0]), "=r"(r[1]), "=r"(r[2]), "=r"(r[3]) : "r"(addr));
}
__device__ __forceinline__ void cpa16(unsigned dst, const void* src) {
    asm volatile("cp.async.cg.shared.global [%0], [%1], 16;" :: "r"(dst), "l"(src));
}
__device__ __forceinline__ void cpa16_ca(unsigned dst, const void* src) {
    asm volatile("cp.async.ca.shared.global [%0], [%1], 16;" :: "r"(dst), "l"(src));
}
__device__ __forceinline__ void cpa_commit() { asm volatile("cp.async.commit_group;"); }
template <int N> __device__ __forceinline__ void cpa_wait() {
    asm volatile("cp.async.wait_group %0;" :: "n"(N));
}
__device__ __forceinline__ unsigned smem_u32(const void* p) {
    return (unsigned)__cvta_generic_to_shared(p);
}
__device__ __forceinline__ unsigned packh2(float a, float b) {
    __half2 h = __floats2half2_rn(a, b);
    return *(unsigned*)&h;
}

// ---------------------------------------------------------------------------
// merged prepass (single launch): blockIdx partitions three jobs.
//   [0, NB_CVT)                : hs fp32 -> fp16
//   [NB_CVT, +NB_TQ)           : qkv_w  [768][2304] -> qkv_wt  [2304][768] fp16
//   [NB_CVT+NB_TQ, +NB_TP)     : proj_w [768][768]  -> proj_wt [768][768]  fp16
// all jobs use 256 threads.
// ---------------------------------------------------------------------------
#define NB_CVT (MROWS * EMB / 4 / 256)          // 6144
#define NB_TQ  ((E3 / 32) * (EMB / 32))         // 72*24 = 1728
#define NB_TP  ((EMB / 32) * (EMB / 32))        // 24*24 = 576

__global__ __launch_bounds__(256) void prepass_kernel(
    const float* __restrict__ hs,     __half* __restrict__ hs16,
    const float* __restrict__ qkv_w,  __half* __restrict__ qkvwt,
    const float* __restrict__ proj_w, __half* __restrict__ projwt)
{
    const int bid = blockIdx.x;
    const int tid = threadIdx.x;

    if (bid < NB_CVT) {
        int i = bid * 256 + tid;
        float4 v = ((const float4*)hs)[i];
        __half2* d2 = (__half2*)hs16;
        d2[i * 2]     = __floats2half2_rn(v.x, v.y);
        d2[i * 2 + 1] = __floats2half2_rn(v.z, v.w);
        return;
    }

    // transpose jobs: W[k][n] -> Wt[n][k], 32x32 tiles, 256 threads (32x8)
    const float* W;
    __half* Wt;
    int K, N, tile;
    if (bid < NB_CVT + NB_TQ) {
        W = qkv_w; Wt = qkvwt; K = EMB; N = E3; tile = bid - NB_CVT;
    } else {
        W = proj_w; Wt = projwt; K = EMB; N = EMB; tile = bid - NB_CVT - NB_TQ;
    }
    const int ntx = N / 32;
    const int n0 = (tile % ntx) * 32;
    const int k0 = (tile / ntx) * 32;
    const int tx = tid & 31;
    const int ty = tid >> 5;                      // 0..7

    __shared__ float t[32][33];
#pragma unroll
    for (int i = 0; i < 4; i++)
        t[ty + i * 8][tx] = W[(size_t)(k0 + ty + i * 8) * N + n0 + tx];
    __syncthreads();
#pragma unroll
    for (int i = 0; i < 4; i++)
        Wt[(size_t)(n0 + ty + i * 8) * K + k0 + tx] = __float2half_rn(t[tx][ty + i * 8]);
}

// ---------------------------------------------------------------------------
// fp16 GEMM (R14 config: CTA 64x128, BK=32, 3-stage ring, wait<1>,
// warp tile 32x32, __launch_bounds__(256,3) -> 3 CTAs/SM, stride-40 smem).
// R17 delta: A-tile fills use cp.async.ca — co-resident CTAs (x-major order)
// usually share blockIdx.y, so A refills hit L1. B stays .cg.
// ---------------------------------------------------------------------------
template <bool QKV>
__global__ __launch_bounds__(256, 3) void gemm_f16_kernel(
    const __half* __restrict__ A, const __half* __restrict__ Bt,
    const float* __restrict__ bias, void* __restrict__ Cv, int N, int K)
{
    extern __shared__ __half dsm[];
    const unsigned aB = smem_u32(dsm);
    const unsigned bB = aB + 3 * 64 * 40 * 2;
    const unsigned aStage = 64 * 40 * 2;
    const unsigned bStage = 128 * 40 * 2;

    const int tid  = threadIdx.x;
    const int lane = tid & 31;
    const int wid  = tid >> 5;
    const int wm   = wid >> 2;
    const int wn   = wid & 3;
    const int r0   = lane >> 2;
    const int c0   = lane & 3;
    const int rowBase = blockIdx.y * 64;
    const int colBase = blockIdx.x * 128;

    const int a_row = tid >> 2;
    const int a_ch  = tid & 3;
    const int b_row = tid >> 1;
    const int b_ch  = (tid & 1) * 2;

    const __half* Ap = A  + (size_t)(rowBase + a_row) * K + a_ch * 8;
    const __half* Bp = Bt + (size_t)(colBase + b_row) * K + b_ch * 8;

    const unsigned aDst = (unsigned)(a_row * 40 + a_ch * 8) * 2;
    const unsigned bDst = (unsigned)(b_row * 40 + b_ch * 8) * 2;

    float acc[2][8][4];
#pragma unroll
    for (int i = 0; i < 2; i++)
#pragma unroll
        for (int j = 0; j < 8; j++)
#pragma unroll
            for (int e = 0; e < 4; e++) acc[i][j][e] = 0.f;

    const int nkt = K / 32;

#pragma unroll
    for (int t = 0; t < 2; t++) {
        cpa16_ca(aB + t * aStage + aDst, Ap + t * 32);
        cpa16(bB + t * bStage + bDst,      Bp + t * 32);
        cpa16(bB + t * bStage + bDst + 16, Bp + t * 32 + 8);
        cpa_commit();
    }

    const unsigned fragRow = (unsigned)(lane & 15);
    const unsigned fragK   = (unsigned)((lane >> 4) << 3);

    for (int kt = 0; kt < nkt; kt++) {
        if (kt + 1 < nkt) cpa_wait<1>(); else cpa_wait<0>();
        __syncthreads();

        if (kt + 2 < nkt) {
            const int s2 = (kt + 2) % 3;
            cpa16_ca(aB + s2 * aStage + aDst, Ap + (kt + 2) * 32);
            cpa16(bB + s2 * bStage + bDst,      Bp + (kt + 2) * 32);
            cpa16(bB + s2 * bStage + bDst + 16, Bp + (kt + 2) * 32 + 8);
            cpa_commit();
        }

        const unsigned as = aB + (kt % 3) * aStage;
        const unsigned bs = bB + (kt % 3) * bStage;
#pragma unroll
        for (int ks = 0; ks < 32; ks += 16) {
            unsigned af[2][4], bf[2][4];
#pragma unroll
            for (int mt = 0; mt < 2; mt++)
                ldm_x4(af[mt], as + ((wm * 32 + mt * 16 + fragRow) * 40 + ks + fragK) * 2);
#pragma unroll
            for (int nb = 0; nb < 2; nb++)
                ldm_x4(bf[nb], bs + ((wn * 32 + nb * 16 + fragRow) * 40 + ks + fragK) * 2);
#pragma unroll
            for (int mt = 0; mt < 2; mt++)
#pragma unroll
                for (int nb = 0; nb < 2; nb++)
#pragma unroll
                    for (int nt2 = 0; nt2 < 2; nt2++) {
                        unsigned b2[2] = {bf[nb][nt2], bf[nb][2 + nt2]};
                        mma_f16(acc[mt][nb * 2 + nt2], af[mt], b2);
                    }
        }
    }

#pragma unroll
    for (int nn = 0; nn < 4; nn++) {
        int col = colBase + wn * 32 + (nn >> 1) * 16 + (nn & 1) * 8 + (c0 << 1);
        float2 bv = *(const float2*)(bias + col);
        // QKV: Q columns get SCALE*log2e for base-2 softmax downstream
        float sc = (QKV && col < EMB) ? QSCALE : 1.0f;
#pragma unroll
        for (int mt = 0; mt < 2; mt++) {
            int row = rowBase + wm * 32 + mt * 16 + r0;
            float x0 = (acc[mt][nn][0] + bv.x) * sc;
            float x1 = (acc[mt][nn][1] + bv.y) * sc;
            float x2 = (acc[mt][nn][2] + bv.x) * sc;
            float x3 = (acc[mt][nn][3] + bv.y) * sc;
            if (QKV) {
                __half2* C = (__half2*)Cv;
                C[((size_t)row * N + col) >> 1]       = __floats2half2_rn(x0, x1);
                C[((size_t)(row + 8) * N + col) >> 1] = __floats2half2_rn(x2, x3);
            } else {
                float* C = (float*)Cv;
                *(float2*)(C + (size_t)row * N + col)       = make_float2(x0, x1);
                *(float2*)(C + (size_t)(row + 8) * N + col) = make_float2(x2, x3);
            }
        }
    }
}

// ---------------------------------------------------------------------------
// fp16 flash attention, 3-stage K/V ring, register-resident P.
// R17 delta: softmax in base-2 domain (Q pre-scaled by SCALE*log2e in the
// QKV epilogue; exp2f replaces __expf -> drops one FFMA per exponential).
// ---------------------------------------------------------------------------
__global__ __launch_bounds__(256, 2) void attn_f16_kernel(const __half* __restrict__ qkv,
                                                          __half* __restrict__ ctx)
{
    extern __shared__ __half asm_[];
    const unsigned qsB = smem_u32(asm_);               // [128][72]
    const unsigned kB  = qsB + 128 * 72 * 2;           // 3 x [64][72]
    const unsigned vB  = kB + 3 * 64 * 72 * 2;         // 3 x [64][72]
    const unsigned kvStage = 64 * 72 * 2;

    const int tid  = threadIdx.x;
    const int lane = tid & 31;
    const int w    = tid >> 5;

    const int qt = blockIdx.x;
    const int h  = blockIdx.y;
    const int b  = blockIdx.z;

    const unsigned fragRow = (unsigned)(lane & 15);
    const unsigned fragK   = (unsigned)((lane >> 4) << 3);
    const int r0 = lane >> 2;
    const int c0 = lane & 3;
    const int qrow = w * 16 + r0;

    // ---- load Q tile ----
    const __half* qg = qkv + (size_t)(b * SEQ + qt * 128) * E3 + h * HDIM;
    {
        int row = tid >> 1;
        int off = (tid & 1) * 4;
#pragma unroll
        for (int i = 0; i < 4; i++)
            cpa16(qsB + (unsigned)(row * 72 + (off + i) * 8) * 2,
                  qg + (size_t)row * E3 + (off + i) * 8);
        cpa_commit();
        cpa_wait<0>();
        __syncthreads();
    }

    unsigned qf[4][4];
#pragma unroll
    for (int ks = 0; ks < 4; ks++)
        ldm_x4(qf[ks], qsB + ((w * 16 + fragRow) * 72 + ks * 16 + fragK) * 2);

    float accO[8][4];
#pragma unroll
    for (int nt = 0; nt < 8; nt++)
#pragma unroll
        for (int e = 0; e < 4; e++) accO[nt][e] = 0.f;
    float m0 = -1e30f, m1 = -1e30f, l0 = 0.f, l1 = 0.f;

    const __half* kg = qkv + (size_t)b * SEQ * E3 + EMB     + h * HDIM;
    const __half* vg = qkv + (size_t)b * SEQ * E3 + 2 * EMB + h * HDIM;

    const int ld_row = tid >> 2;
    const int ld_off = (tid & 3) * 2;
    const size_t ldbase = (size_t)ld_row * E3 + ld_off * 8;
    const unsigned dOff = (unsigned)(ld_row * 72 + ld_off * 8) * 2;

#pragma unroll
    for (int t = 0; t < 2; t++) {
        const __half* kb = kg + (size_t)(t * 64) * E3 + ldbase;
        const __half* vb = vg + (size_t)(t * 64) * E3 + ldbase;
        cpa16(kB + t * kvStage + dOff,      kb);
        cpa16(kB + t * kvStage + dOff + 16, kb + 8);
        cpa16(vB + t * kvStage + dOff,      vb);
        cpa16(vB + t * kvStage + dOff + 16, vb + 8);
        cpa_commit();
    }

    for (int kt = 0; kt < 16; kt++) {
        if (kt + 1 < 16) cpa_wait<1>(); else cpa_wait<0>();
        __syncthreads();

        if (kt + 2 < 16) {
            const int s2 = (kt + 2) % 3;
            const __half* kb = kg + (size_t)((kt + 2) * 64) * E3 + ldbase;
            const __half* vb = vg + (size_t)((kt + 2) * 64) * E3 + ldbase;
            cpa16(kB + s2 * kvStage + dOff,      kb);
            cpa16(kB + s2 * kvStage + dOff + 16, kb + 8);
            cpa16(vB + s2 * kvStage + dOff,      vb);
            cpa16(vB + s2 * kvStage + dOff + 16, vb + 8);
            cpa_commit();
        }

        const unsigned ksS = kB + (kt % 3) * kvStage;
        const unsigned vsS = vB + (kt % 3) * kvStage;

        // ---- S = Q K^T (scores already in log2 domain via Q prescale) ----
        float accS[8][4];
#pragma unroll
        for (int nt = 0; nt < 8; nt++)
#pragma unroll
            for (int e = 0; e < 4; e++) accS[nt][e] = 0.f;

#pragma unroll
        for (int ks = 0; ks < 4; ks++) {
#pragma unroll
            for (int np = 0; np < 4; np++) {
                unsigned bf[4];
                ldm_x4(bf, ksS + ((np * 16 + fragRow) * 72 + ks * 16 + fragK) * 2);
                unsigned b0[2] = {bf[0], bf[2]};
                unsigned b1[2] = {bf[1], bf[3]};
                mma_f16(accS[np * 2],     qf[ks], b0);
                mma_f16(accS[np * 2 + 1], qf[ks], b1);
            }
        }

        // ---- online softmax, base-2 ----
        float mx0 = -1e30f, mx1 = -1e30f;
#pragma unroll
        for (int nt = 0; nt < 8; nt++) {
            mx0 = fmaxf(mx0, fmaxf(accS[nt][0], accS[nt][1]));
            mx1 = fmaxf(mx1, fmaxf(accS[nt][2], accS[nt][3]));
        }
#pragma unroll
        for (int off = 1; off < 4; off <<= 1) {
            mx0 = fmaxf(mx0, __shfl_xor_sync(0xffffffffu, mx0, off));
            mx1 = fmaxf(mx1, __shfl_xor_sync(0xffffffffu, mx1, off));
        }
        float mn0 = fmaxf(m0, mx0), mn1 = fmaxf(m1, mx1);
        float alpha0 = exp2f(m0 - mn0), alpha1 = exp2f(m1 - mn1);
        m0 = mn0; m1 = mn1;

        // ---- P in registers (D-frag layout == A-frag layout) ----
        unsigned pP[8][2];
        float s0 = 0.f, s1 = 0.f;
#pragma unroll
        for (int nt = 0; nt < 8; nt++) {
            float p0 = exp2f(accS[nt][0] - mn0);
            float p1 = exp2f(accS[nt][1] - mn0);
            float p2 = exp2f(accS[nt][2] - mn1);
            float p3 = exp2f(accS[nt][3] - mn1);
            s0 += p0 + p1;
            s1 += p2 + p3;
            pP[nt][0] = packh2(p0, p1);
            pP[nt][1] = packh2(p2, p3);
        }
#pragma unroll
        for (int off = 1; off < 4; off <<= 1) {
            s0 += __shfl_xor_sync(0xffffffffu, s0, off);
            s1 += __shfl_xor_sync(0xffffffffu, s1, off);
        }
        l0 = l0 * alpha0 + s0;
        l1 = l1 * alpha1 + s1;
#pragma unroll
        for (int nt = 0; nt < 8; nt++) {
            accO[nt][0] *= alpha0; accO[nt][1] *= alpha0;
            accO[nt][2] *= alpha1; accO[nt][3] *= alpha1;
        }

        // ---- O += P V ----
#pragma unroll
        for (int ks = 0; ks < 4; ks++) {
            unsigned pf[4] = {pP[2 * ks][0], pP[2 * ks][1],
                              pP[2 * ks + 1][0], pP[2 * ks + 1][1]};
#pragma unroll
            for (int np = 0; np < 4; np++) {
                unsigned bf[4];
                ldm_x4_t(bf, vsS + ((ks * 16 + fragRow) * 72 + np * 16 + fragK) * 2);
                unsigned b0[2] = {bf[0], bf[1]};
                unsigned b1[2] = {bf[2], bf[3]};
                mma_f16(accO[np * 2],     pf, b0);
                mma_f16(accO[np * 2 + 1], pf, b1);
            }
        }
    }

    // ---- normalize + write ctx16 ----
    float inv0 = 1.f / l0, inv1 = 1.f / l1;
    __half2* ob = (__half2*)(ctx + (size_t)(b * SEQ + qt * 128) * EMB + h * HDIM);
#pragma unroll
    for (int nt = 0; nt < 8; nt++) {
        int col = nt * 8 + (c0 << 1);
        ob[((size_t)qrow * EMB + col) >> 1] =
            __floats2half2_rn(accO[nt][0] * inv0, accO[nt][1] * inv0);
        ob[((size_t)(qrow + 8) * EMB + col) >> 1] =
            __floats2half2_rn(accO[nt][2] * inv1, accO[nt][3] * inv1);
    }
}

// ---------------------------------------------------------------------------
extern "C" void kernel_launch(void* const* d_in, const int* in_sizes, int n_in,
                              void* d_out, int out_size)
{
    const float* hs     = (const float*)d_in[0];
    const float* qkv_w  = (const float*)d_in[1];
    const float* qkv_b  = (const float*)d_in[2];
    const float* proj_w = (const float*)d_in[3];
    const float* proj_b = (const float*)d_in[4];
    float* out = (float*)d_out;

    __half *hs16, *qkvwt, *projwt, *qkv16, *ctx16;
    cudaGetSymbolAddress((void**)&hs16,   g_hs16);
    cudaGetSymbolAddress((void**)&qkvwt,  g_qkvwt);
    cudaGetSymbolAddress((void**)&projwt, g_projwt);
    cudaGetSymbolAddress((void**)&qkv16,  g_qkv16);
    cudaGetSymbolAddress((void**)&ctx16,  g_ctx16);

    const int gemm_smem = 3 * (64 + 128) * 40 * 2;                // 46080 B
    const int attn_smem = (128 * 72 + 6 * 64 * 72) * 2;           // 73728 B
    cudaFuncSetAttribute(gemm_f16_kernel<true>,
                         cudaFuncAttributeMaxDynamicSharedMemorySize, gemm_smem);
    cudaFuncSetAttribute(gemm_f16_kernel<false>,
                         cudaFuncAttributeMaxDynamicSharedMemorySize, gemm_smem);
    cudaFuncSetAttribute(attn_f16_kernel,
                         cudaFuncAttributeMaxDynamicSharedMemorySize, attn_smem);

    // 0) merged prepass (single launch)
    prepass_kernel<<<NB_CVT + NB_TQ + NB_TP, 256>>>(hs, hs16, qkv_w, qkvwt, proj_w, projwt);

    // 1) QKV projection (fp16 out, Q pre-scaled by SCALE*log2e)
    gemm_f16_kernel<true><<<dim3(E3 / 128, MROWS / 64), 256, gemm_smem>>>(
        hs16, qkvwt, qkv_b, qkv16, E3, EMB);

    // 2) fp16 flash attention (register-resident P, base-2 softmax)
    attn_f16_kernel<<<dim3(SEQ / 128, NHEADS, BATCH), 256, attn_smem>>>(qkv16, ctx16);

    // 3) output projection (fp32 out)
    gemm_f16_kernel<false><<<dim3(EMB / 128, MROWS / 64), 256, gemm_smem>>>(
        ctx16, projwt, proj_b, out, EMB, EMB);
}